// round 1
// baseline (speedup 1.0000x reference)
#include <cuda_runtime.h>
#include <cuda_bf16.h>

// Idx2PixelLayer: bilinear gather from visible[2048,2048,8] at 1e6 coords.
// out[n,ch] = bilerp of the 4 pixels at (floor-modded) coords.
//
// Reference semantics:
//   c = floormod(coords - 1, dims - 4) + 1        (dims = 2048 -> modulus 2044)
//   i = floor(c); d = c - i
//   top_left = v[i0, i1], top_right = v[i0+1, i1]
//   bottom_left = v[i0, i1+1], bottom_right = v[i0+1, i1+1]
//   mid_top    = top_right    + d0*(top_left    - top_right)
//   mid_bottom = bottom_right + d0*(bottom_left - bottom_right)
//   out = mid_bottom + d1*(mid_top - mid_bottom)
//   zero row if c0 > 2048 (never true, kept for exactness)

static constexpr int HW    = 2048;
static constexpr int CH    = 8;
static constexpr float MODV = 2044.0f;   // H - 4
static constexpr float DIMF = 2048.0f;

__global__ __launch_bounds__(256)
void idx2pixel_kernel(const float* __restrict__ coords,
                      const float* __restrict__ visible,
                      float* __restrict__ out,
                      int n)
{
    int t = blockIdx.x * blockDim.x + threadIdx.x;
    if (t >= n) return;

    float2 co = reinterpret_cast<const float2*>(coords)[t];

    // floor-mod (python semantics) then +1
    float c0 = fmodf(co.x - 1.0f, MODV); if (c0 < 0.0f) c0 += MODV; c0 += 1.0f;
    float c1 = fmodf(co.y - 1.0f, MODV); if (c1 < 0.0f) c1 += MODV; c1 += 1.0f;

    float f0 = floorf(c0), f1 = floorf(c1);
    float d0 = c0 - f0,   d1 = c1 - f1;
    int i0 = (int)f0, i1 = (int)f1;

    // visible[r][col] starts at (r*2048 + col)*8 floats; pixel = 2 float4s.
    // cols i1 and i1+1 are contiguous -> 4 consecutive float4 per row.
    const float4* rowA = reinterpret_cast<const float4*>(
        visible + ((size_t)i0 * HW + i1) * CH);
    const float4* rowB = rowA + (size_t)HW * CH / 4;   // +1 row = +4096 float4

    // top_left (i0, i1)
    float4 tl0 = rowA[0], tl1 = rowA[1];
    // bottom_left (i0, i1+1)
    float4 bl0 = rowA[2], bl1 = rowA[3];
    // top_right (i0+1, i1)
    float4 tr0 = rowB[0], tr1 = rowB[1];
    // bottom_right (i0+1, i1+1)
    float4 br0 = rowB[2], br1 = rowB[3];

    bool zero = (c0 > DIMF);   // reference checks only dim 0
    float w0 = zero ? 0.0f : d0;
    float w1 = zero ? 0.0f : d1;

    float o[8];
    {
        const float* tl = &tl0.x; const float* tr = &tr0.x;
        const float* bl = &bl0.x; const float* br = &br0.x;
        #pragma unroll
        for (int k = 0; k < 4; k++) {
            float mt = tr[k] + w0 * (tl[k] - tr[k]);
            float mb = br[k] + w0 * (bl[k] - br[k]);
            o[k] = mb + w1 * (mt - mb);
        }
        tl = &tl1.x; tr = &tr1.x; bl = &bl1.x; br = &br1.x;
        #pragma unroll
        for (int k = 0; k < 4; k++) {
            float mt = tr[k] + w0 * (tl[k] - tr[k]);
            float mb = br[k] + w0 * (bl[k] - br[k]);
            o[4 + k] = mb + w1 * (mt - mb);
        }
    }
    if (zero) {
        #pragma unroll
        for (int k = 0; k < 8; k++) o[k] = 0.0f;
    }

    float4* dst = reinterpret_cast<float4*>(out + (size_t)t * CH);
    dst[0] = make_float4(o[0], o[1], o[2], o[3]);
    dst[1] = make_float4(o[4], o[5], o[6], o[7]);
}

extern "C" void kernel_launch(void* const* d_in, const int* in_sizes, int n_in,
                              void* d_out, int out_size)
{
    const float* coords  = (const float*)d_in[0];   // (N, 2) float32
    const float* visible = (const float*)d_in[1];   // (2048, 2048, 8) float32
    float* out = (float*)d_out;                     // (N, 8) float32

    int n = in_sizes[0] / 2;
    int threads = 256;
    int blocks = (n + threads - 1) / threads;
    idx2pixel_kernel<<<blocks, threads>>>(coords, visible, out, n);
}